// round 2
// baseline (speedup 1.0000x reference)
#include <cuda_runtime.h>
#include <math_constants.h>

#define BETA 100.0f

// Scratch denominator buffer: N*d = 50000*64 = 3.2M floats needed; 4M provided.
// __device__ global is the allocation-free scratch mechanism allowed by the harness.
__device__ __align__(16) float g_denom[1 << 22];

// Ordered float atomic max via sign-split int atomics.
// For f >= 0 the int bit pattern is order-isomorphic to the float; for f < 0 the
// unsigned pattern is reverse-ordered (max -> umin). Mixing is safe given
// init = -inf (0xFF800000): any stored non-negative beats any negative candidate
// in both views.
__device__ __forceinline__ void atomicMaxF(float* addr, float v) {
    if (v >= 0.0f) {
        atomicMax((int*)addr, __float_as_int(v));
    } else {
        atomicMin((unsigned int*)addr, __float_as_uint(v));
    }
}

// ---------------------------------------------------------------------------
// Kernel 0: init M_v to -inf and denom scratch to 0 (float4 stores).
// ---------------------------------------------------------------------------
__global__ void k_init(float4* __restrict__ Mv, int n4) {
    int i = blockIdx.x * blockDim.x + threadIdx.x;
    if (i >= n4) return;
    Mv[i] = make_float4(-CUDART_INF_F, -CUDART_INF_F, -CUDART_INF_F, -CUDART_INF_F);
    reinterpret_cast<float4*>(g_denom)[i] = make_float4(0.f, 0.f, 0.f, 0.f);
}

// ---------------------------------------------------------------------------
// Kernel 1: scatter-max. One thread per float4 chunk (16 chunks per edge, d=64).
// Test-then-atomic: __ldcg reads a value that is <= the true current value
// (values only increase; atomics bypass L1), so skipping when m <= cur is
// always safe and prunes most atomics under ~25-way average contention.
// ---------------------------------------------------------------------------
__global__ void k_max(const float4* __restrict__ M, const int* __restrict__ dest,
                      float* __restrict__ Mv, int nChunks) {
    int tid = blockIdx.x * blockDim.x + threadIdx.x;
    if (tid >= nChunks) return;
    int e = tid >> 4;          // edge index
    int c = tid & 15;          // float4 chunk within the 64-wide row
    int dst = __ldg(dest + e);
    float4 m = __ldg(M + tid); // M is [E,64] row-major => float4 index == tid
    float* base = Mv + (size_t)dst * 64 + c * 4;
    float4 cur = __ldcg(reinterpret_cast<const float4*>(base));
    if (m.x > cur.x) atomicMaxF(base + 0, m.x);
    if (m.y > cur.y) atomicMaxF(base + 1, m.y);
    if (m.z > cur.z) atomicMaxF(base + 2, m.z);
    if (m.w > cur.w) atomicMaxF(base + 3, m.w);
}

// ---------------------------------------------------------------------------
// Kernel 2: denominator accumulation. exp(BETA*(m - mv)) <= 1, denom >= 1.
// Vectorized 16B reduction: 4x fewer LTS atomic transactions than scalar.
// ---------------------------------------------------------------------------
__global__ void k_sum(const float4* __restrict__ M, const int* __restrict__ dest,
                      const float* __restrict__ Mv, int nChunks) {
    int tid = blockIdx.x * blockDim.x + threadIdx.x;
    if (tid >= nChunks) return;
    int e = tid >> 4;
    int c = tid & 15;
    int dst = __ldg(dest + e);
    float4 m = __ldg(M + tid);
    float4 mv = __ldg(reinterpret_cast<const float4*>(Mv + (size_t)dst * 64) + c);
    float ex = __expf(BETA * (m.x - mv.x));
    float ey = __expf(BETA * (m.y - mv.y));
    float ez = __expf(BETA * (m.z - mv.z));
    float ew = __expf(BETA * (m.w - mv.w));
    float* dptr = g_denom + (size_t)dst * 64 + (size_t)c * 4;
    asm volatile("red.global.add.v4.f32 [%0], {%1, %2, %3, %4};"
                 :: "l"(dptr), "f"(ex), "f"(ey), "f"(ez), "f"(ew)
                 : "memory");
}

// ---------------------------------------------------------------------------
// Kernel 3: write w = exp(BETA*(m - mv)) / denom. Recomputes exp (MUFU is ~free)
// instead of staging z, saving a 320MB stream.
// ---------------------------------------------------------------------------
__global__ void k_w(const float4* __restrict__ M, const int* __restrict__ dest,
                    const float* __restrict__ Mv, float4* __restrict__ w,
                    int nChunks) {
    int tid = blockIdx.x * blockDim.x + threadIdx.x;
    if (tid >= nChunks) return;
    int e = tid >> 4;
    int c = tid & 15;
    int dst = __ldg(dest + e);
    float4 m = __ldg(M + tid);
    float4 mv = __ldg(reinterpret_cast<const float4*>(Mv + (size_t)dst * 64) + c);
    float4 dn = *(reinterpret_cast<const float4*>(g_denom + (size_t)dst * 64) + c);
    float4 out;
    out.x = __fdividef(__expf(BETA * (m.x - mv.x)), dn.x);
    out.y = __fdividef(__expf(BETA * (m.y - mv.y)), dn.y);
    out.z = __fdividef(__expf(BETA * (m.z - mv.z)), dn.z);
    out.w = __fdividef(__expf(BETA * (m.w - mv.w)), dn.w);
    w[tid] = out;
}

// ---------------------------------------------------------------------------
// Host launcher. Inputs (metadata order): M [E,d] f32, dest [E] i32, dim_size.
// Output layout: [M_v (N*d) | w (E*d)] as float32.
// N derived from out_size so the device dim_size scalar is never needed on host.
// ---------------------------------------------------------------------------
extern "C" void kernel_launch(void* const* d_in, const int* in_sizes, int n_in,
                              void* d_out, int out_size) {
    const float* M   = (const float*)d_in[0];
    const int* dest  = (const int*)d_in[1];
    const long long Md = in_sizes[0];        // E*d
    const int E = in_sizes[1];
    const int d = (int)(Md / (long long)E);  // 64
    const int N = (int)(((long long)out_size - Md) / d);

    float* Mv = (float*)d_out;
    float* w  = (float*)d_out + (size_t)N * d;

    const int TB = 256;

    // init M_v and denom scratch
    int n4 = (N * d) / 4;
    k_init<<<(n4 + TB - 1) / TB, TB>>>((float4*)Mv, n4);

    // per-chunk passes (d == 64 layout: 16 float4 chunks per edge)
    int nChunks = E * (d / 4);
    int nBlocks = (nChunks + TB - 1) / TB;
    k_max<<<nBlocks, TB>>>((const float4*)M, dest, Mv, nChunks);
    k_sum<<<nBlocks, TB>>>((const float4*)M, dest, Mv, nChunks);
    k_w  <<<nBlocks, TB>>>((const float4*)M, dest, Mv, (float4*)w, nChunks);
}

// round 4
// speedup vs baseline: 1.7420x; 1.7420x over previous
#include <cuda_runtime.h>
#include <math_constants.h>

#define BETA 100.0f

// ---------------------------------------------------------------------------
// Static scratch (allocation-free per harness rules).
// Problem instance: E = 1,250,000 edges, N = 50,000 nodes, d = 64.
// Capacities sized with headroom.
// ---------------------------------------------------------------------------
#define MAXN 65536
#define MAXE 2000000
#define SCAN_B 1024

__device__ int g_counts[MAXN];
__device__ int g_offsets[MAXN + 1];
__device__ int g_cursor[MAXN];
__device__ int g_aux[1024];
__device__ int g_auxscan[1024];
__device__ int g_edge_idx[MAXE];

// ---------------------------------------------------------------------------
// Preamble: counting sort of edge indices by dest (index-only, ~15MB traffic).
// ---------------------------------------------------------------------------
__global__ void k_zero(int N) {
    int i = blockIdx.x * blockDim.x + threadIdx.x;
    if (i < N) g_counts[i] = 0;
}

__global__ void k_hist(const int* __restrict__ dest, int E) {
    int i = blockIdx.x * blockDim.x + threadIdx.x;
    if (i < E) atomicAdd(&g_counts[__ldg(dest + i)], 1);
}

// Per-chunk exclusive scan (Hillis-Steele in smem) + chunk totals to g_aux.
__global__ void k_scan1(int N) {
    __shared__ int sh[SCAN_B];
    int i = blockIdx.x * SCAN_B + threadIdx.x;
    int v = (i < N) ? g_counts[i] : 0;
    sh[threadIdx.x] = v;
    __syncthreads();
    #pragma unroll
    for (int off = 1; off < SCAN_B; off <<= 1) {
        int t = (threadIdx.x >= off) ? sh[threadIdx.x - off] : 0;
        __syncthreads();
        sh[threadIdx.x] += t;
        __syncthreads();
    }
    if (i < N) g_offsets[i] = sh[threadIdx.x] - v;     // exclusive within chunk
    if (threadIdx.x == SCAN_B - 1) g_aux[blockIdx.x] = sh[SCAN_B - 1];
}

// Serial scan of chunk totals (<=64 chunks for N=50k; trivial).
__global__ void k_scan2(int nChunk) {
    if (threadIdx.x == 0) {
        int run = 0;
        for (int c = 0; c < nChunk; c++) { g_auxscan[c] = run; run += g_aux[c]; }
    }
}

// Add chunk bases; mirror into cursor; cap with offsets[N] = E.
__global__ void k_scan3(int N, int E) {
    int i = blockIdx.x * SCAN_B + threadIdx.x;
    if (i < N) {
        int o = g_offsets[i] + g_auxscan[blockIdx.x];
        g_offsets[i] = o;
        g_cursor[i] = o;
    }
    if (i == 0) g_offsets[N] = E;
}

__global__ void k_scatter(const int* __restrict__ dest, int E) {
    int i = blockIdx.x * blockDim.x + threadIdx.x;
    if (i < E) {
        int d = __ldg(dest + i);
        int pos = atomicAdd(&g_cursor[d], 1);
        g_edge_idx[pos] = i;
    }
}

// ---------------------------------------------------------------------------
// Main kernel: one 64-thread block per node, thread = column.
// Edge indices for the node are staged once into smem (up to 128; expected
// max count over 50k nodes at mean 25 is ~55, so the fallback path is cold).
// Sweep 1: column max over the node's edges (gather, DRAM).
// Sweep 2: sum of exp (re-reads hit L1/L2 — per-node set is ~6.4KB, hot).
// Sweep 3: w = exp * rcp(sum), coalesced 256B scatter per edge.
// No value atomics anywhere. seg_max(BETA*M) = BETA*seg_max(M), so one max
// serves both outputs; exponent <= 0 and denom >= 1 keep __expf safe.
// ---------------------------------------------------------------------------
#define EIDX_CAP 128

__global__ void __launch_bounds__(64) k_node(const float* __restrict__ M,
                                             float* __restrict__ Mv,
                                             float* __restrict__ w) {
    __shared__ int sh_idx[EIDX_CAP];
    int node = blockIdx.x;
    int tid = threadIdx.x;                 // column 0..63
    int s = g_offsets[node];
    int e = g_offsets[node + 1];
    int cnt = e - s;
    int cached = (cnt < EIDX_CAP) ? cnt : EIDX_CAP;

    for (int i = tid; i < cached; i += 64) sh_idx[i] = g_edge_idx[s + i];
    __syncthreads();

    float mx = -CUDART_INF_F;
    for (int i = 0; i < cached; i++)
        mx = fmaxf(mx, __ldg(M + (size_t)sh_idx[i] * 64 + tid));
    for (int i = s + cached; i < e; i++)
        mx = fmaxf(mx, __ldg(M + (size_t)g_edge_idx[i] * 64 + tid));
    Mv[(size_t)node * 64 + tid] = mx;

    float sum = 0.f;
    for (int i = 0; i < cached; i++)
        sum += __expf(BETA * (M[(size_t)sh_idx[i] * 64 + tid] - mx));
    for (int i = s + cached; i < e; i++)
        sum += __expf(BETA * (M[(size_t)g_edge_idx[i] * 64 + tid] - mx));
    float inv = __frcp_rn(sum);            // empty node: never used (no writes)

    for (int i = 0; i < cached; i++) {
        int ed = sh_idx[i];
        float z = __expf(BETA * (M[(size_t)ed * 64 + tid] - mx));
        w[(size_t)ed * 64 + tid] = z * inv;
    }
    for (int i = s + cached; i < e; i++) {
        int ed = g_edge_idx[i];
        float z = __expf(BETA * (M[(size_t)ed * 64 + tid] - mx));
        w[(size_t)ed * 64 + tid] = z * inv;
    }
}

// ---------------------------------------------------------------------------
// Host launcher. Inputs (metadata order): M [E,d] f32, dest [E] i32, dim_size.
// Output layout: [M_v (N*d) | w (E*d)] float32. N derived from out_size.
// ---------------------------------------------------------------------------
extern "C" void kernel_launch(void* const* d_in, const int* in_sizes, int n_in,
                              void* d_out, int out_size) {
    const float* M  = (const float*)d_in[0];
    const int* dest = (const int*)d_in[1];
    const long long Md = in_sizes[0];            // E*d
    const int E = in_sizes[1];
    const int d = (int)(Md / (long long)E);      // 64
    const int N = (int)(((long long)out_size - Md) / d);

    float* Mv = (float*)d_out;
    float* w  = (float*)d_out + (size_t)N * d;

    const int TB = 256;
    int nChunk = (N + SCAN_B - 1) / SCAN_B;
    int eBlocks = (E + TB - 1) / TB;

    k_zero   <<<(N + TB - 1) / TB, TB>>>(N);
    k_hist   <<<eBlocks, TB>>>(dest, E);
    k_scan1  <<<nChunk, SCAN_B>>>(N);
    k_scan2  <<<1, 32>>>(nChunk);
    k_scan3  <<<nChunk, SCAN_B>>>(N, E);
    k_scatter<<<eBlocks, TB>>>(dest, E);
    k_node   <<<N, 64>>>(M, Mv, w);
}